// round 15
// baseline (speedup 1.0000x reference)
#include <cuda_runtime.h>

// fm: (1, 256, 256, 256) fp32 NHWC; rois: (2000, 5) int32 [b, x, y, w, h]; pool = 7.
#define FM_W 256
#define FM_C 256
#define POOLSZ 7
#define NCELL 49
#define NBUCKET 256

__device__ int g_perm[4096];

// ---- Kernel A: spatial binning (16px tiles of ROI center), 1 block. ----
// hist -> parallel scan -> scatter. Within-bucket order is nondeterministic,
// but each ROI writes only its own output slice, so results are unaffected.
__global__ void bin_rois_kernel(const int* __restrict__ rois, int n)
{
    __shared__ int hist[NBUCKET];
    __shared__ int base[NBUCKET];
    __shared__ int warpsum[8];
    int tid = threadIdx.x;   // 256

    hist[tid] = 0;
    __syncthreads();

    for (int i = tid; i < n; i += 256) {
        int x = rois[i * 5 + 1], y = rois[i * 5 + 2];
        int w = rois[i * 5 + 3], h = rois[i * 5 + 4];
        int b = (((y + (h >> 1)) >> 4) << 4) | ((x + (w >> 1)) >> 4);
        atomicAdd(&hist[b], 1);
    }
    __syncthreads();

    // Exclusive scan over 256 entries: warp-level shuffle scan + warp offsets.
    {
        int v = hist[tid];
        int lane = tid & 31, warp = tid >> 5;
        int incl = v;
        #pragma unroll
        for (int d = 1; d < 32; d <<= 1) {
            int t = __shfl_up_sync(0xffffffffu, incl, d);
            if (lane >= d) incl += t;
        }
        if (lane == 31) warpsum[warp] = incl;
        __syncthreads();
        if (tid == 0) {
            int acc = 0;
            #pragma unroll
            for (int wv = 0; wv < 8; wv++) { int t = warpsum[wv]; warpsum[wv] = acc; acc += t; }
        }
        __syncthreads();
        base[tid] = incl - v + warpsum[warp];   // exclusive prefix
    }
    __syncthreads();

    for (int i = tid; i < n; i += 256) {
        int x = rois[i * 5 + 1], y = rois[i * 5 + 2];
        int w = rois[i * 5 + 3], h = rois[i * 5 + 4];
        int b = (((y + (h >> 1)) >> 4) << 4) | ((x + (w >> 1)) >> 4);
        int pos = atomicAdd(&base[b], 1);
        g_perm[pos] = i;
    }
}

// ---- Kernel B: pooling. 512 threads = 2 half-blocks, each one spatially-
// adjacent ROI, running CONCURRENTLY so overlapping reads merge in L1. ----
__global__ __launch_bounds__(512) void roi_pool_kernel(
    const float* __restrict__ fm,      // [H, W, C]
    const int* __restrict__ rois,      // [N, 5]
    float* __restrict__ out,           // [N, 7, 7, C]
    int n_rois)
{
    int tid  = threadIdx.x;
    int half = tid >> 8;       // 0 or 1
    int htid = tid & 255;

    __shared__ int   sx0[2][POOLSZ], sx1[2][POOLSZ], sy0[2][POOLSZ], sy1[2][POOLSZ];
    __shared__ float sfx[2][POOLSZ], sfy[2][POOLSZ];
    __shared__ int4   sIdx[2][NCELL];
    __shared__ float4 sWt[2][NCELL];

    int slot = blockIdx.x * 2 + half;
    bool active = slot < n_rois;
    int roi = active ? g_perm[slot] : 0;

    if (active && htid < 2 * POOLSZ) {
        int  p   = (htid >= POOLSZ) ? htid - POOLSZ : htid;
        bool isx = htid < POOLSZ;
        int start = rois[roi * 5 + (isx ? 1 : 2)];
        int len   = rois[roi * 5 + (isx ? 3 : 4)];
        float lf = (float)len;
        float f = ((float)p + 0.5f) * (lf / (float)POOLSZ) - 0.5f;
        f = fminf(fmaxf(f, 0.0f), lf - 1.0f);
        int i0 = (int)floorf(f);
        int i1 = min(i0 + 1, len - 1);
        float fr = f - (float)i0;
        if (isx) { sx0[half][p] = start + i0; sx1[half][p] = start + i1; sfx[half][p] = fr; }
        else     { sy0[half][p] = start + i0; sy1[half][p] = start + i1; sfy[half][p] = fr; }
    }
    __syncthreads();

    if (active && htid < NCELL) {
        int py = htid / POOLSZ;
        int px = htid - py * POOLSZ;
        int y0 = sy0[half][py], y1 = sy1[half][py];
        int x0 = sx0[half][px], x1 = sx1[half][px];
        float fy = sfy[half][py], fx = sfx[half][px];
        float ofx = 1.0f - fx, ofy = 1.0f - fy;
        int4 idx;
        idx.x = (y0 * FM_W + x0) * (FM_C / 4);
        idx.y = (y0 * FM_W + x1) * (FM_C / 4);
        idx.z = (y1 * FM_W + x0) * (FM_C / 4);
        idx.w = (y1 * FM_W + x1) * (FM_C / 4);
        sIdx[half][htid] = idx;
        float4 w;
        w.x = ofx * ofy;
        w.y = fx  * ofy;
        w.z = ofx * fy;
        w.w = fx  * fy;
        sWt[half][htid] = w;
    }
    __syncthreads();

    if (!active) return;

    int c  = htid & 63;       // channel float4 index 0..63
    int ty = htid >> 6;       // cell-group 0..3

    const float4* f4 = (const float4*)fm;
    float4* o4 = (float4*)out + (size_t)roi * NCELL * (FM_C / 4);

    #pragma unroll 4
    for (int cell = ty; cell < NCELL; cell += 4) {
        int4   idx = sIdx[half][cell];    // broadcast LDS.128
        float4 w   = sWt[half][cell];     // broadcast LDS.128

        const float4 g00 = __ldg(f4 + idx.x + c);
        const float4 g01 = __ldg(f4 + idx.y + c);
        const float4 g10 = __ldg(f4 + idx.z + c);
        const float4 g11 = __ldg(f4 + idx.w + c);

        float4 r;
        r.x = g00.x * w.x + g01.x * w.y + g10.x * w.z + g11.x * w.w;
        r.y = g00.y * w.x + g01.y * w.y + g10.y * w.z + g11.y * w.w;
        r.z = g00.z * w.x + g01.z * w.y + g10.z * w.z + g11.z * w.w;
        r.w = g00.w * w.x + g01.w * w.y + g10.w * w.z + g11.w * w.w;

        // Streaming store: output written once, never read — evict first.
        __stcs(&o4[cell * (FM_C / 4) + c], r);
    }
}

extern "C" void kernel_launch(void* const* d_in, const int* in_sizes, int n_in,
                              void* d_out, int out_size)
{
    const float* fm  = (const float*)d_in[0];
    const int* rois  = (const int*)d_in[1];
    float* out       = (float*)d_out;

    int n_rois = in_sizes[1] / 5;

    bin_rois_kernel<<<1, 256>>>(rois, n_rois);
    int grid = (n_rois + 1) / 2;
    roi_pool_kernel<<<grid, 512>>>(fm, rois, out, n_rois);
}

// round 16
// speedup vs baseline: 1.2310x; 1.2310x over previous
#include <cuda_runtime.h>

// fm: (1, 256, 256, 256) fp32 NHWC; rois: (2000, 5) int32 [b, x, y, w, h]; pool = 7.
#define FM_W 256
#define FM_C 256
#define POOLSZ 7
#define NCELL 49

__global__ __launch_bounds__(256) void roi_pool_kernel(
    const float* __restrict__ fm,      // [H, W, C]
    const int* __restrict__ rois,      // [N, 5]
    float* __restrict__ out)           // [N, 7, 7, C]
{
    int roi = blockIdx.x;
    int tid = threadIdx.x;

    __shared__ int   sx0[POOLSZ], sx1[POOLSZ], sy0[POOLSZ], sy1[POOLSZ];
    __shared__ float sfx[POOLSZ], sfy[POOLSZ];
    __shared__ int4   sIdx[NCELL];   // float4-unit corner base indices (16B aligned)
    __shared__ float4 sWt[NCELL];    // fused bilinear weights

    if (tid < 2 * POOLSZ) {
        int  p   = (tid >= POOLSZ) ? tid - POOLSZ : tid;
        bool isx = tid < POOLSZ;
        int start = rois[roi * 5 + (isx ? 1 : 2)];
        int len   = rois[roi * 5 + (isx ? 3 : 4)];
        float lf = (float)len;
        float f = ((float)p + 0.5f) * (lf / (float)POOLSZ) - 0.5f;
        f = fminf(fmaxf(f, 0.0f), lf - 1.0f);
        int i0 = (int)floorf(f);
        int i1 = min(i0 + 1, len - 1);
        float fr = f - (float)i0;
        if (isx) { sx0[p] = start + i0; sx1[p] = start + i1; sfx[p] = fr; }
        else     { sy0[p] = start + i0; sy1[p] = start + i1; sfy[p] = fr; }
    }
    __syncthreads();

    if (tid < NCELL) {
        int py = tid / POOLSZ;
        int px = tid - py * POOLSZ;
        int y0 = sy0[py], y1 = sy1[py];
        int x0 = sx0[px], x1 = sx1[px];
        float fy = sfy[py], fx = sfx[px];
        float ofx = 1.0f - fx, ofy = 1.0f - fy;
        int4 idx;
        idx.x = (y0 * FM_W + x0) * (FM_C / 4);
        idx.y = (y0 * FM_W + x1) * (FM_C / 4);
        idx.z = (y1 * FM_W + x0) * (FM_C / 4);
        idx.w = (y1 * FM_W + x1) * (FM_C / 4);
        sIdx[tid] = idx;
        float4 w;
        w.x = ofx * ofy;
        w.y = fx  * ofy;
        w.z = ofx * fy;
        w.w = fx  * fy;
        sWt[tid] = w;
    }
    __syncthreads();

    int lane = tid & 31;      // float4 channel 0..31 (and +32)
    int wp   = tid >> 5;      // warp = cell-group 0..7

    const float4* f4 = (const float4*)fm;
    float4* o4 = (float4*)out + (size_t)roi * NCELL * (FM_C / 4);

    // One warp per cell: 8 independent LDG.128 per iteration (MLP=8).
    for (int cell = wp; cell < NCELL; cell += 8) {
        int4   idx = sIdx[cell];    // broadcast LDS.128
        float4 w   = sWt[cell];     // broadcast LDS.128

        int cA = lane, cB = lane + 32;
        const float4 a00 = __ldg(f4 + idx.x + cA);
        const float4 a01 = __ldg(f4 + idx.y + cA);
        const float4 a10 = __ldg(f4 + idx.z + cA);
        const float4 a11 = __ldg(f4 + idx.w + cA);
        const float4 b00 = __ldg(f4 + idx.x + cB);
        const float4 b01 = __ldg(f4 + idx.y + cB);
        const float4 b10 = __ldg(f4 + idx.z + cB);
        const float4 b11 = __ldg(f4 + idx.w + cB);

        float4 rA, rB;
        rA.x = a00.x * w.x + a01.x * w.y + a10.x * w.z + a11.x * w.w;
        rA.y = a00.y * w.x + a01.y * w.y + a10.y * w.z + a11.y * w.w;
        rA.z = a00.z * w.x + a01.z * w.y + a10.z * w.z + a11.z * w.w;
        rA.w = a00.w * w.x + a01.w * w.y + a10.w * w.z + a11.w * w.w;
        rB.x = b00.x * w.x + b01.x * w.y + b10.x * w.z + b11.x * w.w;
        rB.y = b00.y * w.x + b01.y * w.y + b10.y * w.z + b11.y * w.w;
        rB.z = b00.z * w.x + b01.z * w.y + b10.z * w.z + b11.z * w.w;
        rB.w = b00.w * w.x + b01.w * w.y + b10.w * w.z + b11.w * w.w;

        // Streaming stores: output written once, never read — evict first.
        __stcs(&o4[cell * (FM_C / 4) + cA], rA);
        __stcs(&o4[cell * (FM_C / 4) + cB], rB);
    }
}

extern "C" void kernel_launch(void* const* d_in, const int* in_sizes, int n_in,
                              void* d_out, int out_size)
{
    const float* fm  = (const float*)d_in[0];
    const int* rois  = (const int*)d_in[1];
    float* out       = (float*)d_out;

    int n_rois = in_sizes[1] / 5;

    roi_pool_kernel<<<n_rois, 256>>>(fm, rois, out);
}

// round 17
// speedup vs baseline: 1.2980x; 1.0544x over previous
#include <cuda_runtime.h>

// fm: (1, 256, 256, 256) fp32 NHWC; rois: (2000, 5) int32 [b, x, y, w, h]; pool = 7.
#define FM_W 256
#define FM_C 256
#define POOLSZ 7
#define NCELL 49

__global__ __launch_bounds__(256) void roi_pool_kernel(
    const float* __restrict__ fm,      // [H, W, C]
    const int* __restrict__ rois,      // [N, 5]
    float* __restrict__ out)           // [N, 7, 7, C]
{
    int roi = blockIdx.x;
    int tid = threadIdx.x;

    __shared__ int   sx0[POOLSZ], sx1[POOLSZ], sy0[POOLSZ], sy1[POOLSZ];
    __shared__ float sfx[POOLSZ], sfy[POOLSZ];
    __shared__ int4   sIdx[NCELL];   // float4-unit corner base indices (16B aligned)
    __shared__ float4 sWt[NCELL];    // fused bilinear weights

    if (tid < 2 * POOLSZ) {
        int  p   = (tid >= POOLSZ) ? tid - POOLSZ : tid;
        bool isx = tid < POOLSZ;
        int start = rois[roi * 5 + (isx ? 1 : 2)];
        int len   = rois[roi * 5 + (isx ? 3 : 4)];
        float lf = (float)len;
        float f = ((float)p + 0.5f) * (lf / (float)POOLSZ) - 0.5f;
        f = fminf(fmaxf(f, 0.0f), lf - 1.0f);
        int i0 = (int)floorf(f);
        int i1 = min(i0 + 1, len - 1);
        float fr = f - (float)i0;
        if (isx) { sx0[p] = start + i0; sx1[p] = start + i1; sfx[p] = fr; }
        else     { sy0[p] = start + i0; sy1[p] = start + i1; sfy[p] = fr; }
    }
    __syncthreads();

    if (tid < NCELL) {
        int py = tid / POOLSZ;
        int px = tid - py * POOLSZ;
        int y0 = sy0[py], y1 = sy1[py];
        int x0 = sx0[px], x1 = sx1[px];
        float fy = sfy[py], fx = sfx[px];
        float ofx = 1.0f - fx, ofy = 1.0f - fy;
        int4 idx;
        idx.x = (y0 * FM_W + x0) * (FM_C / 4);
        idx.y = (y0 * FM_W + x1) * (FM_C / 4);
        idx.z = (y1 * FM_W + x0) * (FM_C / 4);
        idx.w = (y1 * FM_W + x1) * (FM_C / 4);
        sIdx[tid] = idx;
        float4 w;
        w.x = ofx * ofy;
        w.y = fx  * ofy;
        w.z = ofx * fy;
        w.w = fx  * fy;
        sWt[tid] = w;
    }
    __syncthreads();

    int lane = tid & 31;      // float4 channel 0..31 (and +32)
    int wp   = tid >> 5;      // warp = cell index group 0..7

    const float4* f4 = (const float4*)fm;
    float4* o4 = (float4*)out + (size_t)roi * NCELL * (FM_C / 4);

    const float4 Z = make_float4(0.f, 0.f, 0.f, 0.f);

    // One warp per cell (MLP up to 8). Zero-weight corners (frac==0 on an
    // axis — guaranteed for all cells when len % 7 == 0, ~14% of ROIs per
    // axis) skip their 1KB load entirely; branch is warp-uniform.
    for (int cell = wp; cell < NCELL; cell += 8) {
        int4   idx = sIdx[cell];    // broadcast LDS.128
        float4 w   = sWt[cell];     // broadcast LDS.128

        // fx==0 <=> w.y==w.w==0 ; fy==0 <=> w.z==w.w==0 (ofx+fx=1, ofy+fy=1)
        bool needX1 = (w.y != 0.0f) || (w.w != 0.0f);
        bool needY1 = (w.z != 0.0f) || (w.w != 0.0f);

        int cA = lane, cB = lane + 32;
        float4 a00 = __ldg(f4 + idx.x + cA);
        float4 b00 = __ldg(f4 + idx.x + cB);
        float4 a01 = Z, b01 = Z, a10 = Z, b10 = Z, a11 = Z, b11 = Z;
        if (needX1) {
            a01 = __ldg(f4 + idx.y + cA);
            b01 = __ldg(f4 + idx.y + cB);
        }
        if (needY1) {
            a10 = __ldg(f4 + idx.z + cA);
            b10 = __ldg(f4 + idx.z + cB);
        }
        if (needX1 && needY1) {
            a11 = __ldg(f4 + idx.w + cA);
            b11 = __ldg(f4 + idx.w + cB);
        }

        float4 rA, rB;
        rA.x = a00.x * w.x + a01.x * w.y + a10.x * w.z + a11.x * w.w;
        rA.y = a00.y * w.x + a01.y * w.y + a10.y * w.z + a11.y * w.w;
        rA.z = a00.z * w.x + a01.z * w.y + a10.z * w.z + a11.z * w.w;
        rA.w = a00.w * w.x + a01.w * w.y + a10.w * w.z + a11.w * w.w;
        rB.x = b00.x * w.x + b01.x * w.y + b10.x * w.z + b11.x * w.w;
        rB.y = b00.y * w.x + b01.y * w.y + b10.y * w.z + b11.y * w.w;
        rB.z = b00.z * w.x + b01.z * w.y + b10.z * w.z + b11.z * w.w;
        rB.w = b00.w * w.x + b01.w * w.y + b10.w * w.z + b11.w * w.w;

        // Streaming stores: output written once, never read — evict first.
        __stcs(&o4[cell * (FM_C / 4) + cA], rA);
        __stcs(&o4[cell * (FM_C / 4) + cB], rB);
    }
}

extern "C" void kernel_launch(void* const* d_in, const int* in_sizes, int n_in,
                              void* d_out, int out_size)
{
    const float* fm  = (const float*)d_in[0];
    const int* rois  = (const int*)d_in[1];
    float* out       = (float*)d_out;

    int n_rois = in_sizes[1] / 5;

    roi_pool_kernel<<<n_rois, 256>>>(fm, rois, out);
}